// round 15
// baseline (speedup 1.0000x reference)
#include <cuda_runtime.h>
#include <cuda_bf16.h>
#include <cuda_fp16.h>
#include <math.h>
#include <stdint.h>

#define NNODES 100000
#define NEDGE 300000
#define NB 25600000ull   // NNODES * 256 elements per slab

// fp32: accumulators: 0:accp 1:acca
__device__ float g_buf[2ull * NB];
// fp16 slabs: 0:Kp 1:Vp 2:qRw 3:qRc 4:Ka 5:Va 6:qRwb
__device__ __half g_bufh[7ull * NB];
__device__ float g_norm[2 * NNODES];
__device__ __half g_acath[2ull * NNODES * 256];   // fp16 A (inputs, then aggs)
__device__ __half g_bcath[9ull * 256 * 256];      // fp16 B, all 9 slabs, k-contig
__device__ float g_biascat[1024 + 768];

// ---------------------------------------------------------------------------
static __device__ __forceinline__ uint32_t s2u(const void* p) {
    uint32_t a;
    asm("{ .reg .u64 t; cvta.to.shared.u64 t, %1; cvt.u32.u64 %0, t; }" : "=r"(a) : "l"(p));
    return a;
}
static __device__ __forceinline__ void cpa16(uint32_t dst, const void* src, int sz) {
    asm volatile("cp.async.cg.shared.global [%0], [%1], 16, %2;"
                 :: "r"(dst), "l"(src), "r"(sz) : "memory");
}
#define CP_COMMIT() asm volatile("cp.async.commit_group;" ::: "memory")
#define CP_WAIT1()  asm volatile("cp.async.wait_group 1;" ::: "memory")
#define CP_WAIT2()  asm volatile("cp.async.wait_group 2;" ::: "memory")

#define LDM4(r, addr) \
    asm volatile("ldmatrix.sync.aligned.m8n8.x4.shared.b16 {%0,%1,%2,%3}, [%4];" \
                 : "=r"((r)[0]), "=r"((r)[1]), "=r"((r)[2]), "=r"((r)[3]) : "r"(addr))

// fp16 operands, f32 accumulate
#define MMA16816F(c, a, b0, b1) \
    asm volatile("mma.sync.aligned.m16n8k16.row.col.f32.f16.f16.f32 " \
                 "{%0,%1,%2,%3}, {%4,%5,%6,%7}, {%8,%9}, {%0,%1,%2,%3};" \
                 : "+f"((c)[0]), "+f"((c)[1]), "+f"((c)[2]), "+f"((c)[3]) \
                 : "r"((a)[0]), "r"((a)[1]), "r"((a)[2]), "r"((a)[3]), "r"(b0), "r"(b1))

// fp16 operands, fp16 accumulate (2x rate)
#define MMA16816H(c, a, b0, b1) \
    asm volatile("mma.sync.aligned.m16n8k16.row.col.f16.f16.f16.f16 " \
                 "{%0,%1}, {%2,%3,%4,%5}, {%6,%7}, {%0,%1};" \
                 : "+r"((c)[0]), "+r"((c)[1]) \
                 : "r"((a)[0]), "r"((a)[1]), "r"((a)[2]), "r"((a)[3]), "r"(b0), "r"(b1))

#define REDV4(addr, v) \
    asm volatile("red.global.add.v4.f32 [%0], {%1,%2,%3,%4};" \
                 :: "l"(addr), "f"((v).x), "f"((v).y), "f"((v).z), "f"((v).w) : "memory")

#define STAGE_B 20480u
#define GEMM_SMEM (3 * 20480)
#define STAGE_O 30720u
#define SCORE_SMEM (3 * 30720)
#define OUT_SMEM (4 * 30720 + 4096)

// ---------------------------------------------------------------------------
// Score GEMM: slabs {0:Kp, 2:qRw, 3:qRc, 4:Ka, 6:qRwb}; 512 threads,
// BM=128 x BN=256, fp16 accum (2x rate), 3-stage. grid.y in [0,5).
// ---------------------------------------------------------------------------
__constant__ int c_gslabs[5] = {0, 2, 3, 4, 6};

__global__ void __launch_bounds__(512, 2) gemm_score(
    const __half* __restrict__ Ah0, const __half* __restrict__ Ah1,
    const __half* __restrict__ Bcath, const float* __restrict__ biascat,
    __half* __restrict__ Chalf, int M)
{
    extern __shared__ __align__(16) uint8_t smem[];
    const uint32_t sbase = s2u(smem);
    const int tid = threadIdx.x;
    const int lane = tid & 31;
    const int wid = tid >> 5;
    const int wm = wid & 3;
    const int wn = wid >> 2;
    const int bm = blockIdx.x * 128;

    const int gslab = c_gslabs[blockIdx.y];
    const int auth = gslab >= 4;
    const int lslab = gslab - (auth ? 4 : 0);
    const float* bias = biascat + (auth ? 1024 : 0) + lslab * 256;
    __half* Ch = Chalf + (size_t)gslab * NB;
    const __half* Ah = auth ? Ah1 : Ah0;
    const __half* Bh = Bcath + (size_t)gslab * 65536;

    const int lrow = tid >> 2;
    const int lch = tid & 3;
    const uint32_t aoffs = (uint32_t)((wm * 32 + (lane & 15)) * 80 + (lane >> 4) * 16);
    const uint32_t boffs = (uint32_t)((wn * 64 + (lane & 7) + ((lane >> 4) << 3)) * 80
                                      + ((lane >> 3) & 1) * 16);

    uint32_t hacc[2][8][2];
#pragma unroll
    for (int i = 0; i < 2; i++)
#pragma unroll
        for (int j = 0; j < 8; j++) { hacc[i][j][0] = 0; hacc[i][j][1] = 0; }

#define LOAD_TILE_S(c, st) do {                                                 \
        uint32_t sA_ = sbase + (uint32_t)(st) * STAGE_O;                        \
        uint32_t sB_ = sA_ + 10240u;                                            \
        int grow_ = bm + lrow;                                                  \
        int cg_ = grow_ < M ? grow_ : (M - 1);                                  \
        cpa16(sA_ + lrow * 80 + lch * 16,                                       \
              (const uint8_t*)Ah + ((size_t)cg_ * 256 + (c) * 32 + lch * 8) * 2,\
              grow_ < M ? 16 : 0);                                              \
        cpa16(sB_ + lrow * 80 + lch * 16,                                       \
              (const uint8_t*)Bh + ((size_t)lrow * 256 + (c) * 32 + lch * 8) * 2, 16); \
        cpa16(sB_ + (lrow + 128) * 80 + lch * 16,                               \
              (const uint8_t*)Bh + ((size_t)(lrow + 128) * 256 + (c) * 32 + lch * 8) * 2, 16); \
    } while (0)

    LOAD_TILE_S(0, 0); CP_COMMIT();
    LOAD_TILE_S(1, 1); CP_COMMIT();

    for (int c = 0; c < 8; c++) {
        CP_WAIT1();
        __syncthreads();
        int nc = c + 2;
        if (nc < 8) LOAD_TILE_S(nc, nc % 3);
        CP_COMMIT();

        uint32_t sA = sbase + (uint32_t)(c % 3) * STAGE_O;
        uint32_t sB = sA + 10240u;
#pragma unroll
        for (int ks = 0; ks < 2; ks++) {
            uint32_t a[2][4];
            LDM4(a[0], sA + aoffs + ks * 32);
            LDM4(a[1], sA + aoffs + 1280 + ks * 32);
            uint32_t b[4][4];
#pragma unroll
            for (int nj = 0; nj < 4; nj++)
                LDM4(b[nj], sB + boffs + nj * 1280 + ks * 32);
#pragma unroll
            for (int mi = 0; mi < 2; mi++)
#pragma unroll
                for (int nj = 0; nj < 4; nj++) {
                    MMA16816H(hacc[mi][nj * 2 + 0], a[mi], b[nj][0], b[nj][1]);
                    MMA16816H(hacc[mi][nj * 2 + 1], a[mi], b[nj][2], b[nj][3]);
                }
        }
    }

#pragma unroll
    for (int mi = 0; mi < 2; mi++) {
        int r0 = bm + wm * 32 + mi * 16 + (lane >> 2);
#pragma unroll
        for (int half = 0; half < 2; half++) {
            int row = r0 + half * 8;
            if (row < M) {
#pragma unroll
                for (int nj = 0; nj < 8; nj++) {
                    int cl = wn * 64 + nj * 8 + (lane & 3) * 2;
                    float2 f = __half22float2(*(__half2*)&hacc[mi][nj][half]);
                    __half2 h = __floats2half2_rn(f.x + bias[cl], f.y + bias[cl + 1]);
                    *(__half2*)(Ch + (size_t)row * 256 + cl) = h;
                }
            }
        }
    }
#undef LOAD_TILE_S
}

// ---------------------------------------------------------------------------
// V GEMM: slabs 1 (Vp) / 5 (Va), f32 accumulate, 3-stage, 256 threads.
// ---------------------------------------------------------------------------
#define LOAD_TILE_H(c, st) do {                                                 \
        uint32_t sA_ = sbase + (uint32_t)(st) * STAGE_B;                        \
        uint32_t sB_ = sA_ + 10240u;                                            \
        _Pragma("unroll")                                                       \
        for (int i_ = 0; i_ < 2; i_++) {                                        \
            int row_ = lrow + i_ * 64;                                          \
            int grow_ = bm + row_;                                              \
            int cg_ = grow_ < M ? grow_ : (M - 1);                              \
            cpa16(sA_ + row_ * 80 + lch * 16,                                   \
                  (const uint8_t*)Ah + ((size_t)cg_ * 256 + (c) * 32 + lch * 8) * 2, \
                  grow_ < M ? 16 : 0);                                          \
            cpa16(sB_ + row_ * 80 + lch * 16,                                   \
                  (const uint8_t*)Bh + ((size_t)(nbase + row_) * 256 + (c) * 32 + lch * 8) * 2, \
                  16);                                                          \
        }                                                                       \
    } while (0)

__global__ void __launch_bounds__(256, 2) gemm_v(
    const __half* __restrict__ Ah0, const __half* __restrict__ Ah1,
    const __half* __restrict__ Bcath, const float* __restrict__ biascat,
    __half* __restrict__ Chalf, int M)
{
    extern __shared__ __align__(16) uint8_t smem[];
    const uint32_t sbase = s2u(smem);
    const int tid = threadIdx.x;
    const int lane = tid & 31;
    const int wid = tid >> 5;
    const int wm = wid & 3;
    const int wn = wid >> 2;
    const int bm = blockIdx.x * 128;

    const int auth = blockIdx.y >> 1;
    const int gslab = auth ? 5 : 1;
    const int nbase = (blockIdx.y & 1) * 128;
    const float* bias = biascat + (auth ? 1024 : 0) + 256;
    __half* Ch = Chalf + (size_t)gslab * NB;
    const __half* Ah = auth ? Ah1 : Ah0;
    const __half* Bh = Bcath + (size_t)gslab * 65536;

    const int lrow = tid >> 2;
    const int lch = tid & 3;
    const uint32_t aoffs = (uint32_t)((wm * 32 + (lane & 15)) * 80 + (lane >> 4) * 16);
    const uint32_t boffs = (uint32_t)((wn * 64 + (lane & 7) + ((lane >> 4) << 3)) * 80
                                      + ((lane >> 3) & 1) * 16);

    float acc[2][8][4];
#pragma unroll
    for (int i = 0; i < 2; i++)
#pragma unroll
        for (int j = 0; j < 8; j++)
#pragma unroll
            for (int q = 0; q < 4; q++) acc[i][j][q] = 0.0f;

    LOAD_TILE_H(0, 0); CP_COMMIT();
    LOAD_TILE_H(1, 1); CP_COMMIT();

    for (int c = 0; c < 8; c++) {
        CP_WAIT1();
        __syncthreads();
        int nc = c + 2;
        if (nc < 8) LOAD_TILE_H(nc, nc % 3);
        CP_COMMIT();

        uint32_t sA = sbase + (uint32_t)(c % 3) * STAGE_B;
        uint32_t sB = sA + 10240u;
#pragma unroll
        for (int ks = 0; ks < 2; ks++) {
            uint32_t a[2][4];
            LDM4(a[0], sA + aoffs + ks * 32);
            LDM4(a[1], sA + aoffs + 1280 + ks * 32);
            uint32_t b[4][4];
#pragma unroll
            for (int nj = 0; nj < 4; nj++)
                LDM4(b[nj], sB + boffs + nj * 1280 + ks * 32);
#pragma unroll
            for (int mi = 0; mi < 2; mi++)
#pragma unroll
                for (int nj = 0; nj < 4; nj++) {
                    MMA16816F(acc[mi][nj * 2 + 0], a[mi], b[nj][0], b[nj][1]);
                    MMA16816F(acc[mi][nj * 2 + 1], a[mi], b[nj][2], b[nj][3]);
                }
        }
    }

#pragma unroll
    for (int mi = 0; mi < 2; mi++) {
        int r0 = bm + wm * 32 + mi * 16 + (lane >> 2);
#pragma unroll
        for (int half = 0; half < 2; half++) {
            int row = r0 + half * 8;
            if (row < M) {
#pragma unroll
                for (int nj = 0; nj < 8; nj++) {
                    int cl = nbase + wn * 64 + nj * 8 + (lane & 3) * 2;
                    float v0 = acc[mi][nj][half * 2 + 0] + bias[cl];
                    float v1 = acc[mi][nj][half * 2 + 1] + bias[cl + 1];
                    __half2 h = __floats2half2_rn(v0, v1);
                    *(__half2*)(Ch + (size_t)row * 256 + cl) = h;
                }
            }
        }
    }
}

// ---------------------------------------------------------------------------
// Output GEMM (fp16 operands, f32 accum, 8 chunks) + residual + LayerNorm.
// ---------------------------------------------------------------------------
struct OutP {
    const __half *A0, *A1, *B0, *B1;
    const float *bo0, *bo1, *res0, *res1, *g0, *g1, *be0, *be1;
};

__global__ void __launch_bounds__(512) gemm_out_ln(
    OutP P, float* __restrict__ outbase, int M)
{
    extern __shared__ __align__(16) uint8_t smem[];
    const uint32_t sbase = s2u(smem);
    float* ssum = (float*)(smem + 4 * STAGE_O);
    float* ssq  = ssum + 512;
    const int tid = threadIdx.x;
    const int lane = tid & 31;
    const int wid = tid >> 5;
    const int wm = wid & 3;
    const int wn = wid >> 2;
    const int bm = blockIdx.x * 128;

    const int a_ = blockIdx.y;
    const __half* Ah = a_ ? P.A1 : P.A0;
    const __half* Bh = a_ ? P.B1 : P.B0;
    const float* bo = a_ ? P.bo1 : P.bo0;
    const float* res = a_ ? P.res1 : P.res0;
    const float* g = a_ ? P.g1 : P.g0;
    const float* be = a_ ? P.be1 : P.be0;
    float* out = outbase + (size_t)a_ * NNODES * 256;

    float acc[2][8][4];
#pragma unroll
    for (int i = 0; i < 2; i++)
#pragma unroll
        for (int j = 0; j < 8; j++)
#pragma unroll
            for (int q = 0; q < 4; q++) acc[i][j][q] = 0.0f;

    const int lrow = tid >> 2;
    const int lch = tid & 3;

    const uint32_t aoffs = (uint32_t)((wm * 32 + (lane & 15)) * 80 + (lane >> 4) * 16);
    const uint32_t boffs = (uint32_t)((wn * 64 + (lane & 7) + ((lane >> 4) << 3)) * 80
                                      + ((lane >> 3) & 1) * 16);

#define LOAD_TILE_O(c, st) do {                                                 \
        uint32_t sA_ = sbase + (uint32_t)(st) * STAGE_O;                        \
        uint32_t sB_ = sA_ + 10240u;                                            \
        int grow_ = bm + lrow;                                                  \
        int cg_ = grow_ < M ? grow_ : (M - 1);                                  \
        cpa16(sA_ + lrow * 80 + lch * 16,                                       \
              (const uint8_t*)Ah + ((size_t)cg_ * 256 + (c) * 32 + lch * 8) * 2,\
              grow_ < M ? 16 : 0);                                              \
        cpa16(sB_ + lrow * 80 + lch * 16,                                       \
              (const uint8_t*)Bh + ((size_t)lrow * 256 + (c) * 32 + lch * 8) * 2, 16); \
        cpa16(sB_ + (lrow + 128) * 80 + lch * 16,                               \
              (const uint8_t*)Bh + ((size_t)(lrow + 128) * 256 + (c) * 32 + lch * 8) * 2, 16); \
    } while (0)

    LOAD_TILE_O(0, 0); CP_COMMIT();
    LOAD_TILE_O(1, 1); CP_COMMIT();
    LOAD_TILE_O(2, 2); CP_COMMIT();

    for (int c = 0; c < 8; c++) {
        CP_WAIT2();
        __syncthreads();
        int nc = c + 3;
        if (nc < 8) LOAD_TILE_O(nc, nc & 3);
        CP_COMMIT();

        uint32_t sA = sbase + (uint32_t)(c & 3) * STAGE_O;
        uint32_t sB = sA + 10240u;
#pragma unroll
        for (int ks = 0; ks < 2; ks++) {
            uint32_t a[2][4];
            LDM4(a[0], sA + aoffs + ks * 32);
            LDM4(a[1], sA + aoffs + 1280 + ks * 32);
            uint32_t b[4][4];
#pragma unroll
            for (int nj = 0; nj < 4; nj++)
                LDM4(b[nj], sB + boffs + nj * 1280 + ks * 32);
#pragma unroll
            for (int mi = 0; mi < 2; mi++)
#pragma unroll
                for (int nj = 0; nj < 4; nj++) {
                    MMA16816F(acc[mi][nj * 2 + 0], a[mi], b[nj][0], b[nj][1]);
                    MMA16816F(acc[mi][nj * 2 + 1], a[mi], b[nj][2], b[nj][3]);
                }
        }
    }

    float psum[2][2] = {{0.f, 0.f}, {0.f, 0.f}};
    float psq[2][2]  = {{0.f, 0.f}, {0.f, 0.f}};
#pragma unroll
    for (int mi = 0; mi < 2; mi++)
#pragma unroll
        for (int nj = 0; nj < 8; nj++)
#pragma unroll
            for (int q = 0; q < 4; q++) {
                int half = q >> 1;
                int row = bm + wm * 32 + mi * 16 + (lane >> 2) + half * 8;
                int col = wn * 64 + nj * 8 + (lane & 3) * 2 + (q & 1);
                float v = acc[mi][nj][q] + bo[col];
                if (row < M) v += res[(size_t)row * 256 + col];
                acc[mi][nj][q] = v;
                psum[mi][half] += v;
                psq[mi][half]  += v * v;
            }
#pragma unroll
    for (int mi = 0; mi < 2; mi++)
#pragma unroll
        for (int half = 0; half < 2; half++) {
            float s = psum[mi][half], q = psq[mi][half];
            s += __shfl_xor_sync(0xffffffffu, s, 1);
            s += __shfl_xor_sync(0xffffffffu, s, 2);
            q += __shfl_xor_sync(0xffffffffu, q, 1);
            q += __shfl_xor_sync(0xffffffffu, q, 2);
            if ((lane & 3) == 0) {
                int rl = wm * 32 + mi * 16 + (lane >> 2) + half * 8;
                ssum[rl * 4 + wn] = s;
                ssq[rl * 4 + wn] = q;
            }
        }
    __syncthreads();

    float mean[2][2], rstd[2][2];
#pragma unroll
    for (int mi = 0; mi < 2; mi++)
#pragma unroll
        for (int half = 0; half < 2; half++) {
            int rl = wm * 32 + mi * 16 + (lane >> 2) + half * 8;
            float s = ssum[rl * 4] + ssum[rl * 4 + 1] + ssum[rl * 4 + 2] + ssum[rl * 4 + 3];
            float q = ssq[rl * 4] + ssq[rl * 4 + 1] + ssq[rl * 4 + 2] + ssq[rl * 4 + 3];
            float m = s * (1.0f / 256.0f);
            float var = q * (1.0f / 256.0f) - m * m;
            mean[mi][half] = m;
            rstd[mi][half] = rsqrtf(var + 1e-5f);
        }

#pragma unroll
    for (int mi = 0; mi < 2; mi++)
#pragma unroll
        for (int half = 0; half < 2; half++) {
            int row = bm + wm * 32 + mi * 16 + (lane >> 2) + half * 8;
            if (row < M) {
                float m = mean[mi][half], r = rstd[mi][half];
#pragma unroll
                for (int nj = 0; nj < 8; nj++) {
                    int col = wn * 64 + nj * 8 + (lane & 3) * 2;
                    float v0 = (acc[mi][nj][half * 2 + 0] - m) * r * g[col] + be[col];
                    float v1 = (acc[mi][nj][half * 2 + 1] - m) * r * g[col + 1] + be[col + 1];
                    *(float2*)(out + (size_t)row * 256 + col) = make_float2(v0, v1);
                }
            }
        }
#undef LOAD_TILE_O
}

// ---------------------------------------------------------------------------
struct PrepP {
    const float *Wk_p, *Wv_p, *Wq_p, *bq_p, *Wo_p;
    const float *Wk_a, *Wv_a, *Wq_a, *bq_a, *Wo_a;
    const float *R_w, *R_c, *R_wb;
    const float *bk_p, *bv_p, *bk_a, *bv_a;
};

__global__ void __launch_bounds__(256) prep_all(
    PrepP P, __half* __restrict__ bcath, float* __restrict__ bias)
{
    __shared__ float Rs[8192];
    const int y = blockIdx.y;
    const int x = blockIdx.x;
    const int t = threadIdx.x;

    const float* W = nullptr; const float* R = nullptr;
    const float* bq = nullptr; float* bdst = nullptr;
    switch (y) {
        case 0: W = P.Wk_p; break;
        case 1: W = P.Wv_p; break;
        case 2: W = P.Wq_p; R = P.R_w;  bq = P.bq_p; bdst = bias + 512;  break;
        case 3: W = P.Wq_p; R = P.R_c;  bq = P.bq_p; bdst = bias + 768;  break;
        case 4: W = P.Wk_a; break;
        case 5: W = P.Wv_a; break;
        case 6: W = P.Wq_a; R = P.R_wb; bq = P.bq_a; bdst = bias + 1536; break;
        case 7: W = P.Wo_p; break;
        default: W = P.Wo_a; break;
    }
    __half* Bch = bcath + (size_t)y * 65536;

    if (R) {
        for (int i = t; i < 8192; i += 256) Rs[i] = R[i];
        __syncthreads();
        int h = t >> 5, f = t & 31;
        const float* src = (x < 256) ? &W[x * 256] : bq;
        float v = 0.0f;
#pragma unroll
        for (int d = 0; d < 32; d++)
            v += src[h * 32 + d] * Rs[h * 1024 + d * 32 + f];
        if (x < 256) {
            Bch[(size_t)t * 256 + x] = __float2half(v);
        } else {
            bdst[t] = v;
        }
    } else {
        if (x < 256) {
            Bch[(size_t)x * 256 + t] = __float2half(W[t * 256 + x]);
        } else {
            if (y == 0) bias[t] = P.bk_p[t];
            else if (y == 1) bias[256 + t] = P.bv_p[t];
            else if (y == 4) bias[1024 + t] = P.bk_a[t];
            else if (y == 5) bias[1280 + t] = P.bv_a[t];
        }
    }
}

// ---------------------------------------------------------------------------
// Fused pre-kernel: blocks [0,50000) zero acc+nrm; [50000,100000) split inputs.
// ---------------------------------------------------------------------------
__global__ void pre_kernel(const float* __restrict__ xp, const float* __restrict__ xa,
                           __half* __restrict__ Ah,
                           float* __restrict__ acc, float* __restrict__ nrm) {
    int b = blockIdx.x;
    int t = threadIdx.x;
    if (b < 50000) {
        size_t i = (size_t)b * 256 + t;
        *(float4*)(acc + i * 4) = make_float4(0.f, 0.f, 0.f, 0.f);
        if (i < 2 * NNODES / 4)
            *(float4*)(nrm + i * 4) = make_float4(0.f, 0.f, 0.f, 0.f);
    } else {
        size_t gi = (size_t)(b - 50000) * 256 + t;
        int row = (int)(gi >> 6), c4 = (int)(gi & 63);
        const float* x = (row < NNODES) ? xp : xa;
        int lr = (row < NNODES) ? row : row - NNODES;
        float4 v = *(const float4*)(x + (size_t)lr * 256 + c4 * 4);
        __half2* ap = (__half2*)(Ah + (size_t)row * 256 + c4 * 4);
        ap[0] = __floats2half2_rn(v.x, v.y);
        ap[1] = __floats2half2_rn(v.z, v.w);
    }
}

__global__ void split_agg(const float* __restrict__ acc, const float* __restrict__ nrm,
                          __half* __restrict__ Ah) {
    size_t i = (size_t)blockIdx.x * 256 + threadIdx.x;
    int row = (int)(i >> 6), c4 = (int)(i & 63);
    float inv = 1.0f / fmaxf(nrm[row], 1e-8f);
    float4 v = *(const float4*)(acc + (size_t)row * 256 + c4 * 4);
    __half2* ap = (__half2*)(Ah + (size_t)row * 256 + c4 * 4);
    ap[0] = __floats2half2_rn(v.x * inv, v.y * inv);
    ap[1] = __floats2half2_rn(v.z * inv, v.w * inv);
}

// ---------------------------------------------------------------------------
// Unified edge kernel: relation = blockIdx.x % 3 (block-level interleave;
// per-warp code identical to the proven 3-launch version).
//   r0 (writes):    q=qRw(2)  k=Ka(4) v=Va(5)  acc=accp nrm=np
//   r1 (cites):     q=qRc(3)  k=Kp(0) v=Vp(1)  acc=accp nrm=np
//   r2 (writtenby): q=qRwb(6) k=Kp(0) v=Vp(1)  acc=acca nrm=na
// ---------------------------------------------------------------------------
static __device__ __forceinline__ float dot8h(uint4 a, uint4 b) {
    const __half2* ah = (const __half2*)&a;
    const __half2* bh = (const __half2*)&b;
    float p = 0.0f;
#pragma unroll
    for (int i = 0; i < 4; i++) {
        float2 af = __half22float2(ah[i]);
        float2 bf = __half22float2(bh[i]);
        p += af.x * bf.x + af.y * bf.y;
    }
    return p;
}

struct EdgeP { const int *ei0, *ei1, *ei2; };

__global__ void __launch_bounds__(256) edge_all(
    const __half* __restrict__ bufh, EdgeP E,
    float* __restrict__ accbuf, float* __restrict__ nrmbuf)
{
    const int rel = blockIdx.x % 3;
    const int lb = blockIdx.x / 3;            // local block within relation
    const int nblk = gridDim.x / 3;
    const int lane = threadIdx.x & 31;
    const int warp = (lb * blockDim.x + threadIdx.x) >> 5;
    const int nwarps = (nblk * blockDim.x) >> 5;
    const int off = lane * 8;

    const int* ei = (rel == 0) ? E.ei0 : (rel == 1) ? E.ei1 : E.ei2;
    const __half* qR   = bufh + (size_t)((rel == 0) ? 2 : (rel == 1) ? 3 : 6) * NB;
    const __half* Ksrc = bufh + (size_t)((rel == 0) ? 4 : 0) * NB;
    const __half* Vsrc = bufh + (size_t)((rel == 0) ? 5 : 1) * NB;
    float* accum = accbuf + (size_t)((rel == 2) ? 1 : 0) * NB;
    float* nrm = nrmbuf + ((rel == 2) ? NNODES : 0);

    for (int e = warp; e < NEDGE; e += nwarps) {
        int src = __ldg(&ei[e]);
        int dst = __ldg(&ei[NEDGE + e]);

        uint4 qv = *(const uint4*)(qR + (size_t)dst * 256 + off);
        uint4 kv = *(const uint4*)(Ksrc + (size_t)src * 256 + off);
        float p = dot8h(qv, kv);
        p += __shfl_xor_sync(0xffffffffu, p, 1);
        p += __shfl_xor_sync(0xffffffffu, p, 2);

        float s = p * 0.17677669529663687f;
        s = fminf(fmaxf(s, -5.0f), 5.0f);
        float a = expf(s);

        uint4 vv = *(const uint4*)(Vsrc + (size_t)src * 256 + off);
        const __half2* vh = (const __half2*)&vv;
        float2 f0 = __half22float2(vh[0]);
        float2 f1 = __half22float2(vh[1]);
        float2 f2 = __half22float2(vh[2]);
        float2 f3 = __half22float2(vh[3]);
        float4 v0 = make_float4(f0.x * a, f0.y * a, f1.x * a, f1.y * a);
        float4 v1 = make_float4(f2.x * a, f2.y * a, f3.x * a, f3.y * a);

        float* arow = accum + (size_t)dst * 256 + off;
        REDV4(arow, v0);
        REDV4(arow + 4, v1);

        float w = a;
#pragma unroll
        for (int o = 16; o; o >>= 1) w += __shfl_xor_sync(0xffffffffu, w, o);
        if (lane == 0)
            atomicAdd(&nrm[dst], w * 0.03125f);
    }
}

// ---------------------------------------------------------------------------
extern "C" void kernel_launch(void* const* d_in, const int* in_sizes, int n_in,
                              void* d_out, int out_size) {
    const float* x_p   = (const float*)d_in[0];
    const float* x_a   = (const float*)d_in[1];
    const float* Wk_p  = (const float*)d_in[2];
    const float* bk_p  = (const float*)d_in[3];
    const float* Wq_p  = (const float*)d_in[4];
    const float* bq_p  = (const float*)d_in[5];
    const float* Wv_p  = (const float*)d_in[6];
    const float* bv_p  = (const float*)d_in[7];
    const float* Wo_p  = (const float*)d_in[8];
    const float* bo_p  = (const float*)d_in[9];
    const float* g_p   = (const float*)d_in[10];
    const float* be_p  = (const float*)d_in[11];
    const float* Wk_a  = (const float*)d_in[12];
    const float* bk_a  = (const float*)d_in[13];
    const float* Wq_a  = (const float*)d_in[14];
    const float* bq_a  = (const float*)d_in[15];
    const float* Wv_a  = (const float*)d_in[16];
    const float* bv_a  = (const float*)d_in[17];
    const float* Wo_a  = (const float*)d_in[18];
    const float* bo_a  = (const float*)d_in[19];
    const float* g_a   = (const float*)d_in[20];
    const float* be_a  = (const float*)d_in[21];
    const float* R_w   = (const float*)d_in[22];
    const int*   ei_w  = (const int*)d_in[23];
    const float* R_c   = (const float*)d_in[24];
    const int*   ei_c  = (const int*)d_in[25];
    const float* R_wb  = (const float*)d_in[26];
    const int*   ei_wb = (const int*)d_in[27];
    float* out = (float*)d_out;

    float* buf = nullptr; float* nrm = nullptr; __half* bufh = nullptr;
    __half* acath = nullptr; __half* bcath = nullptr;
    float* bias = nullptr;
    cudaGetSymbolAddress((void**)&buf, g_buf);
    cudaGetSymbolAddress((void**)&bufh, g_bufh);
    cudaGetSymbolAddress((void**)&nrm, g_norm);
    cudaGetSymbolAddress((void**)&acath, g_acath);
    cudaGetSymbolAddress((void**)&bcath, g_bcath);
    cudaGetSymbolAddress((void**)&bias, g_biascat);

    cudaFuncSetAttribute(gemm_score, cudaFuncAttributeMaxDynamicSharedMemorySize, SCORE_SMEM);
    cudaFuncSetAttribute(gemm_v,     cudaFuncAttributeMaxDynamicSharedMemorySize, GEMM_SMEM);
    cudaFuncSetAttribute(gemm_out_ln, cudaFuncAttributeMaxDynamicSharedMemorySize, OUT_SMEM);

    float* accp = buf;

    __half* Ah0 = acath;
    __half* Ah1 = acath + (size_t)NNODES * 256;
#define BCH(i) (bcath + (size_t)(i) * 65536)

    PrepP P = {Wk_p, Wv_p, Wq_p, bq_p, Wo_p,
               Wk_a, Wv_a, Wq_a, bq_a, Wo_a,
               R_w, R_c, R_wb, bk_p, bv_p, bk_a, bv_a};

    // 1: zero + split inputs (fused)
    pre_kernel<<<100000, 256>>>(x_p, x_a, acath, accp, nrm);
    // 2: weight prep
    dim3 pg(257, 9);
    prep_all<<<pg, 256>>>(P, bcath, bias);

    // 3-4: projections
    const int GX = (NNODES + 127) / 128;
    dim3 gs(GX, 5);
    gemm_score<<<gs, 512, SCORE_SMEM>>>(Ah0, Ah1, bcath, bias, bufh, NNODES);
    dim3 gv(GX, 4);
    gemm_v<<<gv, 256, GEMM_SMEM>>>(Ah0, Ah1, bcath, bias, bufh, NNODES);

    // 5: unified edge kernel (rel = bx%3, block-level interleave)
    EdgeP E = {ei_w, ei_c, ei_wb};
    edge_all<<<6144, 256>>>(bufh, E, buf, nrm);

    // 6: normalize + convert aggregates to fp16
    split_agg<<<2 * NNODES / 4, 256>>>(accp, nrm, acath);

    // 7: output GEMM + residual + LayerNorm
    OutP OP = {Ah0, Ah1, BCH(7), BCH(8), bo_p, bo_a, x_p, x_a, g_p, g_a, be_p, be_a};
    dim3 go(GX, 2);
    gemm_out_ln<<<go, 512, OUT_SMEM>>>(OP, out, NNODES);
}

// round 16
// speedup vs baseline: 1.0368x; 1.0368x over previous
#include <cuda_runtime.h>
#include <cuda_bf16.h>
#include <cuda_fp16.h>
#include <math.h>
#include <stdint.h>

#define NNODES 100000
#define NEDGE 300000
#define NB 25600000ull   // NNODES * 256 elements per slab

// fp32: accumulators: 0:accp 1:acca
__device__ float g_buf[2ull * NB];
// fp16 slabs: 0:Kp 1:Vp 2:qRw 3:qRc 4:Ka 5:Va 6:qRwb
__device__ __half g_bufh[7ull * NB];
__device__ float g_norm[2 * NNODES];
__device__ __half g_acath[2ull * NNODES * 256];   // fp16 A (inputs, then aggs)
__device__ __half g_bcath[9ull * 256 * 256];      // fp16 B, all 9 slabs, k-contig
__device__ float g_biascat[1024 + 768];

// ---------------------------------------------------------------------------
static __device__ __forceinline__ uint32_t s2u(const void* p) {
    uint32_t a;
    asm("{ .reg .u64 t; cvta.to.shared.u64 t, %1; cvt.u32.u64 %0, t; }" : "=r"(a) : "l"(p));
    return a;
}
static __device__ __forceinline__ void cpa16(uint32_t dst, const void* src, int sz) {
    asm volatile("cp.async.cg.shared.global [%0], [%1], 16, %2;"
                 :: "r"(dst), "l"(src), "r"(sz) : "memory");
}
#define CP_COMMIT() asm volatile("cp.async.commit_group;" ::: "memory")
#define CP_WAIT1()  asm volatile("cp.async.wait_group 1;" ::: "memory")
#define CP_WAIT2()  asm volatile("cp.async.wait_group 2;" ::: "memory")

#define LDM4(r, addr) \
    asm volatile("ldmatrix.sync.aligned.m8n8.x4.shared.b16 {%0,%1,%2,%3}, [%4];" \
                 : "=r"((r)[0]), "=r"((r)[1]), "=r"((r)[2]), "=r"((r)[3]) : "r"(addr))

// fp16 operands, f32 accumulate
#define MMA16816F(c, a, b0, b1) \
    asm volatile("mma.sync.aligned.m16n8k16.row.col.f32.f16.f16.f32 " \
                 "{%0,%1,%2,%3}, {%4,%5,%6,%7}, {%8,%9}, {%0,%1,%2,%3};" \
                 : "+f"((c)[0]), "+f"((c)[1]), "+f"((c)[2]), "+f"((c)[3]) \
                 : "r"((a)[0]), "r"((a)[1]), "r"((a)[2]), "r"((a)[3]), "r"(b0), "r"(b1))

// fp16 operands, fp16 accumulate (2x rate)
#define MMA16816H(c, a, b0, b1) \
    asm volatile("mma.sync.aligned.m16n8k16.row.col.f16.f16.f16.f16 " \
                 "{%0,%1}, {%2,%3,%4,%5}, {%6,%7}, {%0,%1};" \
                 : "+r"((c)[0]), "+r"((c)[1]) \
                 : "r"((a)[0]), "r"((a)[1]), "r"((a)[2]), "r"((a)[3]), "r"(b0), "r"(b1))

#define REDV4(addr, v) \
    asm volatile("red.global.add.v4.f32 [%0], {%1,%2,%3,%4};" \
                 :: "l"(addr), "f"((v).x), "f"((v).y), "f"((v).z), "f"((v).w) : "memory")

#define STAGE_B 20480u
#define GEMM_SMEM (3 * 20480)
#define STAGE_O 30720u
#define SCORE_SMEM (3 * 30720)
#define OUT_SMEM (4 * 30720 + 4096)

// ---------------------------------------------------------------------------
// Score GEMM: slabs {0:Kp, 2:qRw, 3:qRc, 4:Ka, 6:qRwb}; 512 threads,
// BM=128 x BN=256, fp16 accum (2x rate), 3-stage. grid.y in [0,5).
// ---------------------------------------------------------------------------
__constant__ int c_gslabs[5] = {0, 2, 3, 4, 6};

__global__ void __launch_bounds__(512, 2) gemm_score(
    const __half* __restrict__ Ah0, const __half* __restrict__ Ah1,
    const __half* __restrict__ Bcath, const float* __restrict__ biascat,
    __half* __restrict__ Chalf, int M)
{
    extern __shared__ __align__(16) uint8_t smem[];
    const uint32_t sbase = s2u(smem);
    const int tid = threadIdx.x;
    const int lane = tid & 31;
    const int wid = tid >> 5;
    const int wm = wid & 3;
    const int wn = wid >> 2;
    const int bm = blockIdx.x * 128;

    const int gslab = c_gslabs[blockIdx.y];
    const int auth = gslab >= 4;
    const int lslab = gslab - (auth ? 4 : 0);
    const float* bias = biascat + (auth ? 1024 : 0) + lslab * 256;
    __half* Ch = Chalf + (size_t)gslab * NB;
    const __half* Ah = auth ? Ah1 : Ah0;
    const __half* Bh = Bcath + (size_t)gslab * 65536;

    const int lrow = tid >> 2;
    const int lch = tid & 3;
    const uint32_t aoffs = (uint32_t)((wm * 32 + (lane & 15)) * 80 + (lane >> 4) * 16);
    const uint32_t boffs = (uint32_t)((wn * 64 + (lane & 7) + ((lane >> 4) << 3)) * 80
                                      + ((lane >> 3) & 1) * 16);

    uint32_t hacc[2][8][2];
#pragma unroll
    for (int i = 0; i < 2; i++)
#pragma unroll
        for (int j = 0; j < 8; j++) { hacc[i][j][0] = 0; hacc[i][j][1] = 0; }

#define LOAD_TILE_S(c, st) do {                                                 \
        uint32_t sA_ = sbase + (uint32_t)(st) * STAGE_O;                        \
        uint32_t sB_ = sA_ + 10240u;                                            \
        int grow_ = bm + lrow;                                                  \
        int cg_ = grow_ < M ? grow_ : (M - 1);                                  \
        cpa16(sA_ + lrow * 80 + lch * 16,                                       \
              (const uint8_t*)Ah + ((size_t)cg_ * 256 + (c) * 32 + lch * 8) * 2,\
              grow_ < M ? 16 : 0);                                              \
        cpa16(sB_ + lrow * 80 + lch * 16,                                       \
              (const uint8_t*)Bh + ((size_t)lrow * 256 + (c) * 32 + lch * 8) * 2, 16); \
        cpa16(sB_ + (lrow + 128) * 80 + lch * 16,                               \
              (const uint8_t*)Bh + ((size_t)(lrow + 128) * 256 + (c) * 32 + lch * 8) * 2, 16); \
    } while (0)

    LOAD_TILE_S(0, 0); CP_COMMIT();
    LOAD_TILE_S(1, 1); CP_COMMIT();

    for (int c = 0; c < 8; c++) {
        CP_WAIT1();
        __syncthreads();
        int nc = c + 2;
        if (nc < 8) LOAD_TILE_S(nc, nc % 3);
        CP_COMMIT();

        uint32_t sA = sbase + (uint32_t)(c % 3) * STAGE_O;
        uint32_t sB = sA + 10240u;
#pragma unroll
        for (int ks = 0; ks < 2; ks++) {
            uint32_t a[2][4];
            LDM4(a[0], sA + aoffs + ks * 32);
            LDM4(a[1], sA + aoffs + 1280 + ks * 32);
            uint32_t b[4][4];
#pragma unroll
            for (int nj = 0; nj < 4; nj++)
                LDM4(b[nj], sB + boffs + nj * 1280 + ks * 32);
#pragma unroll
            for (int mi = 0; mi < 2; mi++)
#pragma unroll
                for (int nj = 0; nj < 4; nj++) {
                    MMA16816H(hacc[mi][nj * 2 + 0], a[mi], b[nj][0], b[nj][1]);
                    MMA16816H(hacc[mi][nj * 2 + 1], a[mi], b[nj][2], b[nj][3]);
                }
        }
    }

#pragma unroll
    for (int mi = 0; mi < 2; mi++) {
        int r0 = bm + wm * 32 + mi * 16 + (lane >> 2);
#pragma unroll
        for (int half = 0; half < 2; half++) {
            int row = r0 + half * 8;
            if (row < M) {
#pragma unroll
                for (int nj = 0; nj < 8; nj++) {
                    int cl = wn * 64 + nj * 8 + (lane & 3) * 2;
                    float2 f = __half22float2(*(__half2*)&hacc[mi][nj][half]);
                    __half2 h = __floats2half2_rn(f.x + bias[cl], f.y + bias[cl + 1]);
                    *(__half2*)(Ch + (size_t)row * 256 + cl) = h;
                }
            }
        }
    }
#undef LOAD_TILE_S
}

// ---------------------------------------------------------------------------
// V GEMM: slabs 1 (Vp) / 5 (Va), f32 accumulate, 3-stage, 256 threads.
// ---------------------------------------------------------------------------
#define LOAD_TILE_H(c, st) do {                                                 \
        uint32_t sA_ = sbase + (uint32_t)(st) * STAGE_B;                        \
        uint32_t sB_ = sA_ + 10240u;                                            \
        _Pragma("unroll")                                                       \
        for (int i_ = 0; i_ < 2; i_++) {                                        \
            int row_ = lrow + i_ * 64;                                          \
            int grow_ = bm + row_;                                              \
            int cg_ = grow_ < M ? grow_ : (M - 1);                              \
            cpa16(sA_ + row_ * 80 + lch * 16,                                   \
                  (const uint8_t*)Ah + ((size_t)cg_ * 256 + (c) * 32 + lch * 8) * 2, \
                  grow_ < M ? 16 : 0);                                          \
            cpa16(sB_ + row_ * 80 + lch * 16,                                   \
                  (const uint8_t*)Bh + ((size_t)(nbase + row_) * 256 + (c) * 32 + lch * 8) * 2, \
                  16);                                                          \
        }                                                                       \
    } while (0)

__global__ void __launch_bounds__(256, 2) gemm_v(
    const __half* __restrict__ Ah0, const __half* __restrict__ Ah1,
    const __half* __restrict__ Bcath, const float* __restrict__ biascat,
    __half* __restrict__ Chalf, int M)
{
    extern __shared__ __align__(16) uint8_t smem[];
    const uint32_t sbase = s2u(smem);
    const int tid = threadIdx.x;
    const int lane = tid & 31;
    const int wid = tid >> 5;
    const int wm = wid & 3;
    const int wn = wid >> 2;
    const int bm = blockIdx.x * 128;

    const int auth = blockIdx.y >> 1;
    const int gslab = auth ? 5 : 1;
    const int nbase = (blockIdx.y & 1) * 128;
    const float* bias = biascat + (auth ? 1024 : 0) + 256;
    __half* Ch = Chalf + (size_t)gslab * NB;
    const __half* Ah = auth ? Ah1 : Ah0;
    const __half* Bh = Bcath + (size_t)gslab * 65536;

    const int lrow = tid >> 2;
    const int lch = tid & 3;
    const uint32_t aoffs = (uint32_t)((wm * 32 + (lane & 15)) * 80 + (lane >> 4) * 16);
    const uint32_t boffs = (uint32_t)((wn * 64 + (lane & 7) + ((lane >> 4) << 3)) * 80
                                      + ((lane >> 3) & 1) * 16);

    float acc[2][8][4];
#pragma unroll
    for (int i = 0; i < 2; i++)
#pragma unroll
        for (int j = 0; j < 8; j++)
#pragma unroll
            for (int q = 0; q < 4; q++) acc[i][j][q] = 0.0f;

    LOAD_TILE_H(0, 0); CP_COMMIT();
    LOAD_TILE_H(1, 1); CP_COMMIT();

    for (int c = 0; c < 8; c++) {
        CP_WAIT1();
        __syncthreads();
        int nc = c + 2;
        if (nc < 8) LOAD_TILE_H(nc, nc % 3);
        CP_COMMIT();

        uint32_t sA = sbase + (uint32_t)(c % 3) * STAGE_B;
        uint32_t sB = sA + 10240u;
#pragma unroll
        for (int ks = 0; ks < 2; ks++) {
            uint32_t a[2][4];
            LDM4(a[0], sA + aoffs + ks * 32);
            LDM4(a[1], sA + aoffs + 1280 + ks * 32);
            uint32_t b[4][4];
#pragma unroll
            for (int nj = 0; nj < 4; nj++)
                LDM4(b[nj], sB + boffs + nj * 1280 + ks * 32);
#pragma unroll
            for (int mi = 0; mi < 2; mi++)
#pragma unroll
                for (int nj = 0; nj < 4; nj++) {
                    MMA16816F(acc[mi][nj * 2 + 0], a[mi], b[nj][0], b[nj][1]);
                    MMA16816F(acc[mi][nj * 2 + 1], a[mi], b[nj][2], b[nj][3]);
                }
        }
    }

#pragma unroll
    for (int mi = 0; mi < 2; mi++) {
        int r0 = bm + wm * 32 + mi * 16 + (lane >> 2);
#pragma unroll
        for (int half = 0; half < 2; half++) {
            int row = r0 + half * 8;
            if (row < M) {
#pragma unroll
                for (int nj = 0; nj < 8; nj++) {
                    int cl = nbase + wn * 64 + nj * 8 + (lane & 3) * 2;
                    float v0 = acc[mi][nj][half * 2 + 0] + bias[cl];
                    float v1 = acc[mi][nj][half * 2 + 1] + bias[cl + 1];
                    __half2 h = __floats2half2_rn(v0, v1);
                    *(__half2*)(Ch + (size_t)row * 256 + cl) = h;
                }
            }
        }
    }
}

// ---------------------------------------------------------------------------
// Output GEMM (fp16 operands, f32 accum, 8 chunks) + residual + LayerNorm.
// ---------------------------------------------------------------------------
struct OutP {
    const __half *A0, *A1, *B0, *B1;
    const float *bo0, *bo1, *res0, *res1, *g0, *g1, *be0, *be1;
};

__global__ void __launch_bounds__(512) gemm_out_ln(
    OutP P, float* __restrict__ outbase, int M)
{
    extern __shared__ __align__(16) uint8_t smem[];
    const uint32_t sbase = s2u(smem);
    float* ssum = (float*)(smem + 4 * STAGE_O);
    float* ssq  = ssum + 512;
    const int tid = threadIdx.x;
    const int lane = tid & 31;
    const int wid = tid >> 5;
    const int wm = wid & 3;
    const int wn = wid >> 2;
    const int bm = blockIdx.x * 128;

    const int a_ = blockIdx.y;
    const __half* Ah = a_ ? P.A1 : P.A0;
    const __half* Bh = a_ ? P.B1 : P.B0;
    const float* bo = a_ ? P.bo1 : P.bo0;
    const float* res = a_ ? P.res1 : P.res0;
    const float* g = a_ ? P.g1 : P.g0;
    const float* be = a_ ? P.be1 : P.be0;
    float* out = outbase + (size_t)a_ * NNODES * 256;

    float acc[2][8][4];
#pragma unroll
    for (int i = 0; i < 2; i++)
#pragma unroll
        for (int j = 0; j < 8; j++)
#pragma unroll
            for (int q = 0; q < 4; q++) acc[i][j][q] = 0.0f;

    const int lrow = tid >> 2;
    const int lch = tid & 3;

    const uint32_t aoffs = (uint32_t)((wm * 32 + (lane & 15)) * 80 + (lane >> 4) * 16);
    const uint32_t boffs = (uint32_t)((wn * 64 + (lane & 7) + ((lane >> 4) << 3)) * 80
                                      + ((lane >> 3) & 1) * 16);

#define LOAD_TILE_O(c, st) do {                                                 \
        uint32_t sA_ = sbase + (uint32_t)(st) * STAGE_O;                        \
        uint32_t sB_ = sA_ + 10240u;                                            \
        int grow_ = bm + lrow;                                                  \
        int cg_ = grow_ < M ? grow_ : (M - 1);                                  \
        cpa16(sA_ + lrow * 80 + lch * 16,                                       \
              (const uint8_t*)Ah + ((size_t)cg_ * 256 + (c) * 32 + lch * 8) * 2,\
              grow_ < M ? 16 : 0);                                              \
        cpa16(sB_ + lrow * 80 + lch * 16,                                       \
              (const uint8_t*)Bh + ((size_t)lrow * 256 + (c) * 32 + lch * 8) * 2, 16); \
        cpa16(sB_ + (lrow + 128) * 80 + lch * 16,                               \
              (const uint8_t*)Bh + ((size_t)(lrow + 128) * 256 + (c) * 32 + lch * 8) * 2, 16); \
    } while (0)

    LOAD_TILE_O(0, 0); CP_COMMIT();
    LOAD_TILE_O(1, 1); CP_COMMIT();
    LOAD_TILE_O(2, 2); CP_COMMIT();

    for (int c = 0; c < 8; c++) {
        CP_WAIT2();
        __syncthreads();
        int nc = c + 3;
        if (nc < 8) LOAD_TILE_O(nc, nc & 3);
        CP_COMMIT();

        uint32_t sA = sbase + (uint32_t)(c & 3) * STAGE_O;
        uint32_t sB = sA + 10240u;
#pragma unroll
        for (int ks = 0; ks < 2; ks++) {
            uint32_t a[2][4];
            LDM4(a[0], sA + aoffs + ks * 32);
            LDM4(a[1], sA + aoffs + 1280 + ks * 32);
            uint32_t b[4][4];
#pragma unroll
            for (int nj = 0; nj < 4; nj++)
                LDM4(b[nj], sB + boffs + nj * 1280 + ks * 32);
#pragma unroll
            for (int mi = 0; mi < 2; mi++)
#pragma unroll
                for (int nj = 0; nj < 4; nj++) {
                    MMA16816F(acc[mi][nj * 2 + 0], a[mi], b[nj][0], b[nj][1]);
                    MMA16816F(acc[mi][nj * 2 + 1], a[mi], b[nj][2], b[nj][3]);
                }
        }
    }

    float psum[2][2] = {{0.f, 0.f}, {0.f, 0.f}};
    float psq[2][2]  = {{0.f, 0.f}, {0.f, 0.f}};
#pragma unroll
    for (int mi = 0; mi < 2; mi++)
#pragma unroll
        for (int nj = 0; nj < 8; nj++)
#pragma unroll
            for (int q = 0; q < 4; q++) {
                int half = q >> 1;
                int row = bm + wm * 32 + mi * 16 + (lane >> 2) + half * 8;
                int col = wn * 64 + nj * 8 + (lane & 3) * 2 + (q & 1);
                float v = acc[mi][nj][q] + bo[col];
                if (row < M) v += res[(size_t)row * 256 + col];
                acc[mi][nj][q] = v;
                psum[mi][half] += v;
                psq[mi][half]  += v * v;
            }
#pragma unroll
    for (int mi = 0; mi < 2; mi++)
#pragma unroll
        for (int half = 0; half < 2; half++) {
            float s = psum[mi][half], q = psq[mi][half];
            s += __shfl_xor_sync(0xffffffffu, s, 1);
            s += __shfl_xor_sync(0xffffffffu, s, 2);
            q += __shfl_xor_sync(0xffffffffu, q, 1);
            q += __shfl_xor_sync(0xffffffffu, q, 2);
            if ((lane & 3) == 0) {
                int rl = wm * 32 + mi * 16 + (lane >> 2) + half * 8;
                ssum[rl * 4 + wn] = s;
                ssq[rl * 4 + wn] = q;
            }
        }
    __syncthreads();

    float mean[2][2], rstd[2][2];
#pragma unroll
    for (int mi = 0; mi < 2; mi++)
#pragma unroll
        for (int half = 0; half < 2; half++) {
            int rl = wm * 32 + mi * 16 + (lane >> 2) + half * 8;
            float s = ssum[rl * 4] + ssum[rl * 4 + 1] + ssum[rl * 4 + 2] + ssum[rl * 4 + 3];
            float q = ssq[rl * 4] + ssq[rl * 4 + 1] + ssq[rl * 4 + 2] + ssq[rl * 4 + 3];
            float m = s * (1.0f / 256.0f);
            float var = q * (1.0f / 256.0f) - m * m;
            mean[mi][half] = m;
            rstd[mi][half] = rsqrtf(var + 1e-5f);
        }

#pragma unroll
    for (int mi = 0; mi < 2; mi++)
#pragma unroll
        for (int half = 0; half < 2; half++) {
            int row = bm + wm * 32 + mi * 16 + (lane >> 2) + half * 8;
            if (row < M) {
                float m = mean[mi][half], r = rstd[mi][half];
#pragma unroll
                for (int nj = 0; nj < 8; nj++) {
                    int col = wn * 64 + nj * 8 + (lane & 3) * 2;
                    float v0 = (acc[mi][nj][half * 2 + 0] - m) * r * g[col] + be[col];
                    float v1 = (acc[mi][nj][half * 2 + 1] - m) * r * g[col + 1] + be[col + 1];
                    *(float2*)(out + (size_t)row * 256 + col) = make_float2(v0, v1);
                }
            }
        }
#undef LOAD_TILE_O
}

// ---------------------------------------------------------------------------
struct PrepP {
    const float *Wk_p, *Wv_p, *Wq_p, *bq_p, *Wo_p;
    const float *Wk_a, *Wv_a, *Wq_a, *bq_a, *Wo_a;
    const float *R_w, *R_c, *R_wb;
    const float *bk_p, *bv_p, *bk_a, *bv_a;
};

__global__ void __launch_bounds__(256) prep_all(
    PrepP P, __half* __restrict__ bcath, float* __restrict__ bias)
{
    __shared__ float Rs[8192];
    const int y = blockIdx.y;
    const int x = blockIdx.x;
    const int t = threadIdx.x;

    const float* W = nullptr; const float* R = nullptr;
    const float* bq = nullptr; float* bdst = nullptr;
    switch (y) {
        case 0: W = P.Wk_p; break;
        case 1: W = P.Wv_p; break;
        case 2: W = P.Wq_p; R = P.R_w;  bq = P.bq_p; bdst = bias + 512;  break;
        case 3: W = P.Wq_p; R = P.R_c;  bq = P.bq_p; bdst = bias + 768;  break;
        case 4: W = P.Wk_a; break;
        case 5: W = P.Wv_a; break;
        case 6: W = P.Wq_a; R = P.R_wb; bq = P.bq_a; bdst = bias + 1536; break;
        case 7: W = P.Wo_p; break;
        default: W = P.Wo_a; break;
    }
    __half* Bch = bcath + (size_t)y * 65536;

    if (R) {
        for (int i = t; i < 8192; i += 256) Rs[i] = R[i];
        __syncthreads();
        int h = t >> 5, f = t & 31;
        const float* src = (x < 256) ? &W[x * 256] : bq;
        float v = 0.0f;
#pragma unroll
        for (int d = 0; d < 32; d++)
            v += src[h * 32 + d] * Rs[h * 1024 + d * 32 + f];
        if (x < 256) {
            Bch[(size_t)t * 256 + x] = __float2half(v);
        } else {
            bdst[t] = v;
        }
    } else {
        if (x < 256) {
            Bch[(size_t)x * 256 + t] = __float2half(W[t * 256 + x]);
        } else {
            if (y == 0) bias[t] = P.bk_p[t];
            else if (y == 1) bias[256 + t] = P.bv_p[t];
            else if (y == 4) bias[1024 + t] = P.bk_a[t];
            else if (y == 5) bias[1280 + t] = P.bv_a[t];
        }
    }
}

// ---------------------------------------------------------------------------
// Fused pre-kernel: blocks [0,50000) zero acc+nrm; [50000,100000) split inputs.
// ---------------------------------------------------------------------------
__global__ void pre_kernel(const float* __restrict__ xp, const float* __restrict__ xa,
                           __half* __restrict__ Ah,
                           float* __restrict__ acc, float* __restrict__ nrm) {
    int b = blockIdx.x;
    int t = threadIdx.x;
    if (b < 50000) {
        size_t i = (size_t)b * 256 + t;
        *(float4*)(acc + i * 4) = make_float4(0.f, 0.f, 0.f, 0.f);
        if (i < 2 * NNODES / 4)
            *(float4*)(nrm + i * 4) = make_float4(0.f, 0.f, 0.f, 0.f);
    } else {
        size_t gi = (size_t)(b - 50000) * 256 + t;
        int row = (int)(gi >> 6), c4 = (int)(gi & 63);
        const float* x = (row < NNODES) ? xp : xa;
        int lr = (row < NNODES) ? row : row - NNODES;
        float4 v = *(const float4*)(x + (size_t)lr * 256 + c4 * 4);
        __half2* ap = (__half2*)(Ah + (size_t)row * 256 + c4 * 4);
        ap[0] = __floats2half2_rn(v.x, v.y);
        ap[1] = __floats2half2_rn(v.z, v.w);
    }
}

__global__ void split_agg(const float* __restrict__ acc, const float* __restrict__ nrm,
                          __half* __restrict__ Ah) {
    size_t i = (size_t)blockIdx.x * 256 + threadIdx.x;
    int row = (int)(i >> 6), c4 = (int)(i & 63);
    float inv = 1.0f / fmaxf(nrm[row], 1e-8f);
    float4 v = *(const float4*)(acc + (size_t)row * 256 + c4 * 4);
    __half2* ap = (__half2*)(Ah + (size_t)row * 256 + c4 * 4);
    ap[0] = __floats2half2_rn(v.x * inv, v.y * inv);
    ap[1] = __floats2half2_rn(v.z * inv, v.w * inv);
}

// ---------------------------------------------------------------------------
// Edge kernel (proven 3-launch version): fp16 q/k/v gathers, red.v4 scatter.
// ---------------------------------------------------------------------------
static __device__ __forceinline__ float dot8h(uint4 a, uint4 b) {
    const __half2* ah = (const __half2*)&a;
    const __half2* bh = (const __half2*)&b;
    float p = 0.0f;
#pragma unroll
    for (int i = 0; i < 4; i++) {
        float2 af = __half22float2(ah[i]);
        float2 bf = __half22float2(bh[i]);
        p += af.x * bf.x + af.y * bf.y;
    }
    return p;
}

__global__ void __launch_bounds__(256) edge_kernel(
    const __half* __restrict__ qR, const __half* __restrict__ Ksrc,
    const __half* __restrict__ Vsrc, const int* __restrict__ ei,
    float* __restrict__ accum, float* __restrict__ nrm)
{
    const int lane = threadIdx.x & 31;
    const int warp = (blockIdx.x * blockDim.x + threadIdx.x) >> 5;
    const int nwarps = (gridDim.x * blockDim.x) >> 5;
    const int off = lane * 8;

    for (int e = warp; e < NEDGE; e += nwarps) {
        int src = __ldg(&ei[e]);
        int dst = __ldg(&ei[NEDGE + e]);

        uint4 qv = *(const uint4*)(qR + (size_t)dst * 256 + off);
        uint4 kv = *(const uint4*)(Ksrc + (size_t)src * 256 + off);
        float p = dot8h(qv, kv);
        p += __shfl_xor_sync(0xffffffffu, p, 1);
        p += __shfl_xor_sync(0xffffffffu, p, 2);

        float s = p * 0.17677669529663687f;
        s = fminf(fmaxf(s, -5.0f), 5.0f);
        float a = expf(s);

        uint4 vv = *(const uint4*)(Vsrc + (size_t)src * 256 + off);
        const __half2* vh = (const __half2*)&vv;
        float2 f0 = __half22float2(vh[0]);
        float2 f1 = __half22float2(vh[1]);
        float2 f2 = __half22float2(vh[2]);
        float2 f3 = __half22float2(vh[3]);
        float4 v0 = make_float4(f0.x * a, f0.y * a, f1.x * a, f1.y * a);
        float4 v1 = make_float4(f2.x * a, f2.y * a, f3.x * a, f3.y * a);

        float* arow = accum + (size_t)dst * 256 + off;
        REDV4(arow, v0);
        REDV4(arow + 4, v1);

        float w = a;
#pragma unroll
        for (int o = 16; o; o >>= 1) w += __shfl_xor_sync(0xffffffffu, w, o);
        if (lane == 0)
            atomicAdd(&nrm[dst], w * 0.03125f);
    }
}

// ---------------------------------------------------------------------------
extern "C" void kernel_launch(void* const* d_in, const int* in_sizes, int n_in,
                              void* d_out, int out_size) {
    const float* x_p   = (const float*)d_in[0];
    const float* x_a   = (const float*)d_in[1];
    const float* Wk_p  = (const float*)d_in[2];
    const float* bk_p  = (const float*)d_in[3];
    const float* Wq_p  = (const float*)d_in[4];
    const float* bq_p  = (const float*)d_in[5];
    const float* Wv_p  = (const float*)d_in[6];
    const float* bv_p  = (const float*)d_in[7];
    const float* Wo_p  = (const float*)d_in[8];
    const float* bo_p  = (const float*)d_in[9];
    const float* g_p   = (const float*)d_in[10];
    const float* be_p  = (const float*)d_in[11];
    const float* Wk_a  = (const float*)d_in[12];
    const float* bk_a  = (const float*)d_in[13];
    const float* Wq_a  = (const float*)d_in[14];
    const float* bq_a  = (const float*)d_in[15];
    const float* Wv_a  = (const float*)d_in[16];
    const float* bv_a  = (const float*)d_in[17];
    const float* Wo_a  = (const float*)d_in[18];
    const float* bo_a  = (const float*)d_in[19];
    const float* g_a   = (const float*)d_in[20];
    const float* be_a  = (const float*)d_in[21];
    const float* R_w   = (const float*)d_in[22];
    const int*   ei_w  = (const int*)d_in[23];
    const float* R_c   = (const float*)d_in[24];
    const int*   ei_c  = (const int*)d_in[25];
    const float* R_wb  = (const float*)d_in[26];
    const int*   ei_wb = (const int*)d_in[27];
    float* out = (float*)d_out;

    float* buf = nullptr; float* nrm = nullptr; __half* bufh = nullptr;
    __half* acath = nullptr; __half* bcath = nullptr;
    float* bias = nullptr;
    cudaGetSymbolAddress((void**)&buf, g_buf);
    cudaGetSymbolAddress((void**)&bufh, g_bufh);
    cudaGetSymbolAddress((void**)&nrm, g_norm);
    cudaGetSymbolAddress((void**)&acath, g_acath);
    cudaGetSymbolAddress((void**)&bcath, g_bcath);
    cudaGetSymbolAddress((void**)&bias, g_biascat);

    cudaFuncSetAttribute(gemm_score, cudaFuncAttributeMaxDynamicSharedMemorySize, SCORE_SMEM);
    cudaFuncSetAttribute(gemm_v,     cudaFuncAttributeMaxDynamicSharedMemorySize, GEMM_SMEM);
    cudaFuncSetAttribute(gemm_out_ln, cudaFuncAttributeMaxDynamicSharedMemorySize, OUT_SMEM);

    float* accp = buf;
    float* acca = buf + NB;
    __half* Kph   = bufh + 0 * NB;
    __half* Vph   = bufh + 1 * NB;
    __half* qRwh  = bufh + 2 * NB;
    __half* qRch  = bufh + 3 * NB;
    __half* Kah   = bufh + 4 * NB;
    __half* Vah   = bufh + 5 * NB;
    __half* qRwbh = bufh + 6 * NB;
    float* np_  = nrm;
    float* na_  = nrm + NNODES;

    __half* Ah0 = acath;
    __half* Ah1 = acath + (size_t)NNODES * 256;
#define BCH(i) (bcath + (size_t)(i) * 65536)

    PrepP P = {Wk_p, Wv_p, Wq_p, bq_p, Wo_p,
               Wk_a, Wv_a, Wq_a, bq_a, Wo_a,
               R_w, R_c, R_wb, bk_p, bv_p, bk_a, bv_a};

    // 1: zero + split inputs (fused)
    pre_kernel<<<100000, 256>>>(x_p, x_a, acath, accp, nrm);
    // 2: weight prep
    dim3 pg(257, 9);
    prep_all<<<pg, 256>>>(P, bcath, bias);

    // 3-4: projections
    const int GX = (NNODES + 127) / 128;
    dim3 gs(GX, 5);
    gemm_score<<<gs, 512, SCORE_SMEM>>>(Ah0, Ah1, bcath, bias, bufh, NNODES);
    dim3 gv(GX, 4);
    gemm_v<<<gv, 256, GEMM_SMEM>>>(Ah0, Ah1, bcath, bias, bufh, NNODES);

    // 5-7: edge message passing (3 launches — proven optimum)
    edge_kernel<<<2048, 256>>>(qRwh,  Kah, Vah, ei_w,  accp, np_);
    edge_kernel<<<2048, 256>>>(qRch,  Kph, Vph, ei_c,  accp, np_);
    edge_kernel<<<2048, 256>>>(qRwbh, Kph, Vph, ei_wb, acca, na_);

    // 8: normalize + convert aggregates to fp16
    split_agg<<<2 * NNODES / 4, 256>>>(accp, nrm, acath);

    // 9: output GEMM + residual + LayerNorm
    OutP OP = {Ah0, Ah1, BCH(7), BCH(8), bo_p, bo_a, x_p, x_a, g_p, g_a, be_p, be_a};
    dim3 go(GX, 2);
    gemm_out_ln<<<go, 512, OUT_SMEM>>>(OP, out, NNODES);
}

// round 17
// speedup vs baseline: 1.0373x; 1.0004x over previous
#include <cuda_runtime.h>
#include <cuda_bf16.h>
#include <cuda_fp16.h>
#include <math.h>
#include <stdint.h>

#define NNODES 100000
#define NEDGE 300000
#define NB 25600000ull   // NNODES * 256 elements per slab

// fp32: accumulators: 0:accp 1:acca
__device__ float g_buf[2ull * NB];
// fp16 slabs: 0:Kp 1:Vp 2:qRw 3:qRc 4:Ka 5:Va 6:qRwb
__device__ __half g_bufh[7ull * NB];
__device__ float g_norm[2 * NNODES];
__device__ __half g_acath[2ull * NNODES * 256];   // fp16 A (inputs, then aggs)
__device__ __half g_bcath[9ull * 256 * 256];      // fp16 B, all 9 slabs, k-contig
__device__ float g_biascat[1024 + 768];

// ---------------------------------------------------------------------------
static __device__ __forceinline__ uint32_t s2u(const void* p) {
    uint32_t a;
    asm("{ .reg .u64 t; cvta.to.shared.u64 t, %1; cvt.u32.u64 %0, t; }" : "=r"(a) : "l"(p));
    return a;
}
static __device__ __forceinline__ void cpa16(uint32_t dst, const void* src, int sz) {
    asm volatile("cp.async.cg.shared.global [%0], [%1], 16, %2;"
                 :: "r"(dst), "l"(src), "r"(sz) : "memory");
}
#define CP_COMMIT() asm volatile("cp.async.commit_group;" ::: "memory")
#define CP_WAIT1()  asm volatile("cp.async.wait_group 1;" ::: "memory")
#define CP_WAIT2()  asm volatile("cp.async.wait_group 2;" ::: "memory")

#define LDM4(r, addr) \
    asm volatile("ldmatrix.sync.aligned.m8n8.x4.shared.b16 {%0,%1,%2,%3}, [%4];" \
                 : "=r"((r)[0]), "=r"((r)[1]), "=r"((r)[2]), "=r"((r)[3]) : "r"(addr))

// fp16 operands, f32 accumulate
#define MMA16816F(c, a, b0, b1) \
    asm volatile("mma.sync.aligned.m16n8k16.row.col.f32.f16.f16.f32 " \
                 "{%0,%1,%2,%3}, {%4,%5,%6,%7}, {%8,%9}, {%0,%1,%2,%3};" \
                 : "+f"((c)[0]), "+f"((c)[1]), "+f"((c)[2]), "+f"((c)[3]) \
                 : "r"((a)[0]), "r"((a)[1]), "r"((a)[2]), "r"((a)[3]), "r"(b0), "r"(b1))

// fp16 operands, fp16 accumulate (2x rate)
#define MMA16816H(c, a, b0, b1) \
    asm volatile("mma.sync.aligned.m16n8k16.row.col.f16.f16.f16.f16 " \
                 "{%0,%1}, {%2,%3,%4,%5}, {%6,%7}, {%0,%1};" \
                 : "+r"((c)[0]), "+r"((c)[1]) \
                 : "r"((a)[0]), "r"((a)[1]), "r"((a)[2]), "r"((a)[3]), "r"(b0), "r"(b1))

#define REDV4(addr, v) \
    asm volatile("red.global.add.v4.f32 [%0], {%1,%2,%3,%4};" \
                 :: "l"(addr), "f"((v).x), "f"((v).y), "f"((v).z), "f"((v).w) : "memory")

#define STAGE_B 20480u
#define GEMM_SMEM (3 * 20480)
#define STAGE_O 30720u
#define SCORE_SMEM (3 * 30720)
#define OUT_SMEM (4 * 30720 + 4096)

// ---------------------------------------------------------------------------
// Score GEMM: slabs {0:Kp, 2:qRw, 3:qRc, 4:Ka, 6:qRwb}; 256 threads,
// 8 warps as 2(M)x4(N), warp tile 64x64 (1.0 ldmatrix-matrices per MMA),
// BM=128 x BN=256, fp16 accum (2x rate), 3-stage. grid.y in [0,5).
// ---------------------------------------------------------------------------
__constant__ int c_gslabs[5] = {0, 2, 3, 4, 6};

__global__ void __launch_bounds__(256, 2) gemm_score(
    const __half* __restrict__ Ah0, const __half* __restrict__ Ah1,
    const __half* __restrict__ Bcath, const float* __restrict__ biascat,
    __half* __restrict__ Chalf, int M)
{
    extern __shared__ __align__(16) uint8_t smem[];
    const uint32_t sbase = s2u(smem);
    const int tid = threadIdx.x;
    const int lane = tid & 31;
    const int wid = tid >> 5;
    const int wm = wid & 1;     // 2 warps along M (64 rows each)
    const int wn = wid >> 1;    // 4 warps along N (64 cols each)
    const int bm = blockIdx.x * 128;

    const int gslab = c_gslabs[blockIdx.y];
    const int auth = gslab >= 4;
    const int lslab = gslab - (auth ? 4 : 0);
    const float* bias = biascat + (auth ? 1024 : 0) + lslab * 256;
    __half* Ch = Chalf + (size_t)gslab * NB;
    const __half* Ah = auth ? Ah1 : Ah0;
    const __half* Bh = Bcath + (size_t)gslab * 65536;

    const int lrow = tid >> 2;   // 0..63
    const int lch = tid & 3;
    const uint32_t aoffs = (uint32_t)((wm * 64 + (lane & 15)) * 80 + (lane >> 4) * 16);
    const uint32_t boffs = (uint32_t)((wn * 64 + (lane & 7) + ((lane >> 4) << 3)) * 80
                                      + ((lane >> 3) & 1) * 16);

    uint32_t hacc[4][8][2];
#pragma unroll
    for (int i = 0; i < 4; i++)
#pragma unroll
        for (int j = 0; j < 8; j++) { hacc[i][j][0] = 0; hacc[i][j][1] = 0; }

#define LOAD_TILE_S(c, st) do {                                                 \
        uint32_t sA_ = sbase + (uint32_t)(st) * STAGE_O;                        \
        uint32_t sB_ = sA_ + 10240u;                                            \
        _Pragma("unroll")                                                       \
        for (int i_ = 0; i_ < 2; i_++) {                                        \
            int row_ = lrow + i_ * 64;                                          \
            int grow_ = bm + row_;                                              \
            int cg_ = grow_ < M ? grow_ : (M - 1);                              \
            cpa16(sA_ + row_ * 80 + lch * 16,                                   \
                  (const uint8_t*)Ah + ((size_t)cg_ * 256 + (c) * 32 + lch * 8) * 2, \
                  grow_ < M ? 16 : 0);                                          \
        }                                                                       \
        _Pragma("unroll")                                                       \
        for (int j_ = 0; j_ < 4; j_++) {                                        \
            int brow_ = lrow + j_ * 64;                                         \
            cpa16(sB_ + brow_ * 80 + lch * 16,                                  \
                  (const uint8_t*)Bh + ((size_t)brow_ * 256 + (c) * 32 + lch * 8) * 2, 16); \
        }                                                                       \
    } while (0)

    LOAD_TILE_S(0, 0); CP_COMMIT();
    LOAD_TILE_S(1, 1); CP_COMMIT();

    for (int c = 0; c < 8; c++) {
        CP_WAIT1();
        __syncthreads();
        int nc = c + 2;
        if (nc < 8) LOAD_TILE_S(nc, nc % 3);
        CP_COMMIT();

        uint32_t sA = sbase + (uint32_t)(c % 3) * STAGE_O;
        uint32_t sB = sA + 10240u;
#pragma unroll
        for (int ks = 0; ks < 2; ks++) {
            uint32_t a[4][4];
#pragma unroll
            for (int mi = 0; mi < 4; mi++)
                LDM4(a[mi], sA + aoffs + mi * 1280 + ks * 32);
            uint32_t b[4][4];
#pragma unroll
            for (int nj = 0; nj < 4; nj++)
                LDM4(b[nj], sB + boffs + nj * 1280 + ks * 32);
#pragma unroll
            for (int mi = 0; mi < 4; mi++)
#pragma unroll
                for (int nj = 0; nj < 4; nj++) {
                    MMA16816H(hacc[mi][nj * 2 + 0], a[mi], b[nj][0], b[nj][1]);
                    MMA16816H(hacc[mi][nj * 2 + 1], a[mi], b[nj][2], b[nj][3]);
                }
        }
    }

#pragma unroll
    for (int mi = 0; mi < 4; mi++) {
        int r0 = bm + wm * 64 + mi * 16 + (lane >> 2);
#pragma unroll
        for (int half = 0; half < 2; half++) {
            int row = r0 + half * 8;
            if (row < M) {
#pragma unroll
                for (int nj = 0; nj < 8; nj++) {
                    int cl = wn * 64 + nj * 8 + (lane & 3) * 2;
                    float2 f = __half22float2(*(__half2*)&hacc[mi][nj][half]);
                    __half2 h = __floats2half2_rn(f.x + bias[cl], f.y + bias[cl + 1]);
                    *(__half2*)(Ch + (size_t)row * 256 + cl) = h;
                }
            }
        }
    }
#undef LOAD_TILE_S
}

// ---------------------------------------------------------------------------
// V GEMM: slabs 1 (Vp) / 5 (Va), f32 accumulate, 3-stage, 256 threads.
// ---------------------------------------------------------------------------
#define LOAD_TILE_H(c, st) do {                                                 \
        uint32_t sA_ = sbase + (uint32_t)(st) * STAGE_B;                        \
        uint32_t sB_ = sA_ + 10240u;                                            \
        _Pragma("unroll")                                                       \
        for (int i_ = 0; i_ < 2; i_++) {                                        \
            int row_ = lrow + i_ * 64;                                          \
            int grow_ = bm + row_;                                              \
            int cg_ = grow_ < M ? grow_ : (M - 1);                              \
            cpa16(sA_ + row_ * 80 + lch * 16,                                   \
                  (const uint8_t*)Ah + ((size_t)cg_ * 256 + (c) * 32 + lch * 8) * 2, \
                  grow_ < M ? 16 : 0);                                          \
            cpa16(sB_ + row_ * 80 + lch * 16,                                   \
                  (const uint8_t*)Bh + ((size_t)(nbase + row_) * 256 + (c) * 32 + lch * 8) * 2, \
                  16);                                                          \
        }                                                                       \
    } while (0)

__global__ void __launch_bounds__(256, 2) gemm_v(
    const __half* __restrict__ Ah0, const __half* __restrict__ Ah1,
    const __half* __restrict__ Bcath, const float* __restrict__ biascat,
    __half* __restrict__ Chalf, int M)
{
    extern __shared__ __align__(16) uint8_t smem[];
    const uint32_t sbase = s2u(smem);
    const int tid = threadIdx.x;
    const int lane = tid & 31;
    const int wid = tid >> 5;
    const int wm = wid & 3;
    const int wn = wid >> 2;
    const int bm = blockIdx.x * 128;

    const int auth = blockIdx.y >> 1;
    const int gslab = auth ? 5 : 1;
    const int nbase = (blockIdx.y & 1) * 128;
    const float* bias = biascat + (auth ? 1024 : 0) + 256;
    __half* Ch = Chalf + (size_t)gslab * NB;
    const __half* Ah = auth ? Ah1 : Ah0;
    const __half* Bh = Bcath + (size_t)gslab * 65536;

    const int lrow = tid >> 2;
    const int lch = tid & 3;
    const uint32_t aoffs = (uint32_t)((wm * 32 + (lane & 15)) * 80 + (lane >> 4) * 16);
    const uint32_t boffs = (uint32_t)((wn * 64 + (lane & 7) + ((lane >> 4) << 3)) * 80
                                      + ((lane >> 3) & 1) * 16);

    float acc[2][8][4];
#pragma unroll
    for (int i = 0; i < 2; i++)
#pragma unroll
        for (int j = 0; j < 8; j++)
#pragma unroll
            for (int q = 0; q < 4; q++) acc[i][j][q] = 0.0f;

    LOAD_TILE_H(0, 0); CP_COMMIT();
    LOAD_TILE_H(1, 1); CP_COMMIT();

    for (int c = 0; c < 8; c++) {
        CP_WAIT1();
        __syncthreads();
        int nc = c + 2;
        if (nc < 8) LOAD_TILE_H(nc, nc % 3);
        CP_COMMIT();

        uint32_t sA = sbase + (uint32_t)(c % 3) * STAGE_B;
        uint32_t sB = sA + 10240u;
#pragma unroll
        for (int ks = 0; ks < 2; ks++) {
            uint32_t a[2][4];
            LDM4(a[0], sA + aoffs + ks * 32);
            LDM4(a[1], sA + aoffs + 1280 + ks * 32);
            uint32_t b[4][4];
#pragma unroll
            for (int nj = 0; nj < 4; nj++)
                LDM4(b[nj], sB + boffs + nj * 1280 + ks * 32);
#pragma unroll
            for (int mi = 0; mi < 2; mi++)
#pragma unroll
                for (int nj = 0; nj < 4; nj++) {
                    MMA16816F(acc[mi][nj * 2 + 0], a[mi], b[nj][0], b[nj][1]);
                    MMA16816F(acc[mi][nj * 2 + 1], a[mi], b[nj][2], b[nj][3]);
                }
        }
    }

#pragma unroll
    for (int mi = 0; mi < 2; mi++) {
        int r0 = bm + wm * 32 + mi * 16 + (lane >> 2);
#pragma unroll
        for (int half = 0; half < 2; half++) {
            int row = r0 + half * 8;
            if (row < M) {
#pragma unroll
                for (int nj = 0; nj < 8; nj++) {
                    int cl = nbase + wn * 64 + nj * 8 + (lane & 3) * 2;
                    float v0 = acc[mi][nj][half * 2 + 0] + bias[cl];
                    float v1 = acc[mi][nj][half * 2 + 1] + bias[cl + 1];
                    __half2 h = __floats2half2_rn(v0, v1);
                    *(__half2*)(Ch + (size_t)row * 256 + cl) = h;
                }
            }
        }
    }
}

// ---------------------------------------------------------------------------
// Output GEMM (fp16 operands, f32 accum, 8 chunks) + residual + LayerNorm.
// ---------------------------------------------------------------------------
struct OutP {
    const __half *A0, *A1, *B0, *B1;
    const float *bo0, *bo1, *res0, *res1, *g0, *g1, *be0, *be1;
};

__global__ void __launch_bounds__(512) gemm_out_ln(
    OutP P, float* __restrict__ outbase, int M)
{
    extern __shared__ __align__(16) uint8_t smem[];
    const uint32_t sbase = s2u(smem);
    float* ssum = (float*)(smem + 4 * STAGE_O);
    float* ssq  = ssum + 512;
    const int tid = threadIdx.x;
    const int lane = tid & 31;
    const int wid = tid >> 5;
    const int wm = wid & 3;
    const int wn = wid >> 2;
    const int bm = blockIdx.x * 128;

    const int a_ = blockIdx.y;
    const __half* Ah = a_ ? P.A1 : P.A0;
    const __half* Bh = a_ ? P.B1 : P.B0;
    const float* bo = a_ ? P.bo1 : P.bo0;
    const float* res = a_ ? P.res1 : P.res0;
    const float* g = a_ ? P.g1 : P.g0;
    const float* be = a_ ? P.be1 : P.be0;
    float* out = outbase + (size_t)a_ * NNODES * 256;

    float acc[2][8][4];
#pragma unroll
    for (int i = 0; i < 2; i++)
#pragma unroll
        for (int j = 0; j < 8; j++)
#pragma unroll
            for (int q = 0; q < 4; q++) acc[i][j][q] = 0.0f;

    const int lrow = tid >> 2;
    const int lch = tid & 3;

    const uint32_t aoffs = (uint32_t)((wm * 32 + (lane & 15)) * 80 + (lane >> 4) * 16);
    const uint32_t boffs = (uint32_t)((wn * 64 + (lane & 7) + ((lane >> 4) << 3)) * 80
                                      + ((lane >> 3) & 1) * 16);

#define LOAD_TILE_O(c, st) do {                                                 \
        uint32_t sA_ = sbase + (uint32_t)(st) * STAGE_O;                        \
        uint32_t sB_ = sA_ + 10240u;                                            \
        int grow_ = bm + lrow;                                                  \
        int cg_ = grow_ < M ? grow_ : (M - 1);                                  \
        cpa16(sA_ + lrow * 80 + lch * 16,                                       \
              (const uint8_t*)Ah + ((size_t)cg_ * 256 + (c) * 32 + lch * 8) * 2,\
              grow_ < M ? 16 : 0);                                              \
        cpa16(sB_ + lrow * 80 + lch * 16,                                       \
              (const uint8_t*)Bh + ((size_t)lrow * 256 + (c) * 32 + lch * 8) * 2, 16); \
        cpa16(sB_ + (lrow + 128) * 80 + lch * 16,                               \
              (const uint8_t*)Bh + ((size_t)(lrow + 128) * 256 + (c) * 32 + lch * 8) * 2, 16); \
    } while (0)

    LOAD_TILE_O(0, 0); CP_COMMIT();
    LOAD_TILE_O(1, 1); CP_COMMIT();
    LOAD_TILE_O(2, 2); CP_COMMIT();

    for (int c = 0; c < 8; c++) {
        CP_WAIT2();
        __syncthreads();
        int nc = c + 3;
        if (nc < 8) LOAD_TILE_O(nc, nc & 3);
        CP_COMMIT();

        uint32_t sA = sbase + (uint32_t)(c & 3) * STAGE_O;
        uint32_t sB = sA + 10240u;
#pragma unroll
        for (int ks = 0; ks < 2; ks++) {
            uint32_t a[2][4];
            LDM4(a[0], sA + aoffs + ks * 32);
            LDM4(a[1], sA + aoffs + 1280 + ks * 32);
            uint32_t b[4][4];
#pragma unroll
            for (int nj = 0; nj < 4; nj++)
                LDM4(b[nj], sB + boffs + nj * 1280 + ks * 32);
#pragma unroll
            for (int mi = 0; mi < 2; mi++)
#pragma unroll
                for (int nj = 0; nj < 4; nj++) {
                    MMA16816F(acc[mi][nj * 2 + 0], a[mi], b[nj][0], b[nj][1]);
                    MMA16816F(acc[mi][nj * 2 + 1], a[mi], b[nj][2], b[nj][3]);
                }
        }
    }

    float psum[2][2] = {{0.f, 0.f}, {0.f, 0.f}};
    float psq[2][2]  = {{0.f, 0.f}, {0.f, 0.f}};
#pragma unroll
    for (int mi = 0; mi < 2; mi++)
#pragma unroll
        for (int nj = 0; nj < 8; nj++)
#pragma unroll
            for (int q = 0; q < 4; q++) {
                int half = q >> 1;
                int row = bm + wm * 32 + mi * 16 + (lane >> 2) + half * 8;
                int col = wn * 64 + nj * 8 + (lane & 3) * 2 + (q & 1);
                float v = acc[mi][nj][q] + bo[col];
                if (row < M) v += res[(size_t)row * 256 + col];
                acc[mi][nj][q] = v;
                psum[mi][half] += v;
                psq[mi][half]  += v * v;
            }
#pragma unroll
    for (int mi = 0; mi < 2; mi++)
#pragma unroll
        for (int half = 0; half < 2; half++) {
            float s = psum[mi][half], q = psq[mi][half];
            s += __shfl_xor_sync(0xffffffffu, s, 1);
            s += __shfl_xor_sync(0xffffffffu, s, 2);
            q += __shfl_xor_sync(0xffffffffu, q, 1);
            q += __shfl_xor_sync(0xffffffffu, q, 2);
            if ((lane & 3) == 0) {
                int rl = wm * 32 + mi * 16 + (lane >> 2) + half * 8;
                ssum[rl * 4 + wn] = s;
                ssq[rl * 4 + wn] = q;
            }
        }
    __syncthreads();

    float mean[2][2], rstd[2][2];
#pragma unroll
    for (int mi = 0; mi < 2; mi++)
#pragma unroll
        for (int half = 0; half < 2; half++) {
            int rl = wm * 32 + mi * 16 + (lane >> 2) + half * 8;
            float s = ssum[rl * 4] + ssum[rl * 4 + 1] + ssum[rl * 4 + 2] + ssum[rl * 4 + 3];
            float q = ssq[rl * 4] + ssq[rl * 4 + 1] + ssq[rl * 4 + 2] + ssq[rl * 4 + 3];
            float m = s * (1.0f / 256.0f);
            float var = q * (1.0f / 256.0f) - m * m;
            mean[mi][half] = m;
            rstd[mi][half] = rsqrtf(var + 1e-5f);
        }

#pragma unroll
    for (int mi = 0; mi < 2; mi++)
#pragma unroll
        for (int half = 0; half < 2; half++) {
            int row = bm + wm * 32 + mi * 16 + (lane >> 2) + half * 8;
            if (row < M) {
                float m = mean[mi][half], r = rstd[mi][half];
#pragma unroll
                for (int nj = 0; nj < 8; nj++) {
                    int col = wn * 64 + nj * 8 + (lane & 3) * 2;
                    float v0 = (acc[mi][nj][half * 2 + 0] - m) * r * g[col] + be[col];
                    float v1 = (acc[mi][nj][half * 2 + 1] - m) * r * g[col + 1] + be[col + 1];
                    *(float2*)(out + (size_t)row * 256 + col) = make_float2(v0, v1);
                }
            }
        }
#undef LOAD_TILE_O
}

// ---------------------------------------------------------------------------
struct PrepP {
    const float *Wk_p, *Wv_p, *Wq_p, *bq_p, *Wo_p;
    const float *Wk_a, *Wv_a, *Wq_a, *bq_a, *Wo_a;
    const float *R_w, *R_c, *R_wb;
    const float *bk_p, *bv_p, *bk_a, *bv_a;
};

__global__ void __launch_bounds__(256) prep_all(
    PrepP P, __half* __restrict__ bcath, float* __restrict__ bias)
{
    __shared__ float Rs[8192];
    const int y = blockIdx.y;
    const int x = blockIdx.x;
    const int t = threadIdx.x;

    const float* W = nullptr; const float* R = nullptr;
    const float* bq = nullptr; float* bdst = nullptr;
    switch (y) {
        case 0: W = P.Wk_p; break;
        case 1: W = P.Wv_p; break;
        case 2: W = P.Wq_p; R = P.R_w;  bq = P.bq_p; bdst = bias + 512;  break;
        case 3: W = P.Wq_p; R = P.R_c;  bq = P.bq_p; bdst = bias + 768;  break;
        case 4: W = P.Wk_a; break;
        case 5: W = P.Wv_a; break;
        case 6: W = P.Wq_a; R = P.R_wb; bq = P.bq_a; bdst = bias + 1536; break;
        case 7: W = P.Wo_p; break;
        default: W = P.Wo_a; break;
    }
    __half* Bch = bcath + (size_t)y * 65536;

    if (R) {
        for (int i = t; i < 8192; i += 256) Rs[i] = R[i];
        __syncthreads();
        int h = t >> 5, f = t & 31;
        const float* src = (x < 256) ? &W[x * 256] : bq;
        float v = 0.0f;
#pragma unroll
        for (int d = 0; d < 32; d++)
            v += src[h * 32 + d] * Rs[h * 1024 + d * 32 + f];
        if (x < 256) {
            Bch[(size_t)t * 256 + x] = __float2half(v);
        } else {
            bdst[t] = v;
        }
    } else {
        if (x < 256) {
            Bch[(size_t)x * 256 + t] = __float2half(W[t * 256 + x]);
        } else {
            if (y == 0) bias[t] = P.bk_p[t];
            else if (y == 1) bias[256 + t] = P.bv_p[t];
            else if (y == 4) bias[1024 + t] = P.bk_a[t];
            else if (y == 5) bias[1280 + t] = P.bv_a[t];
        }
    }
}

// ---------------------------------------------------------------------------
// Fused pre-kernel: blocks [0,50000) zero acc+nrm; [50000,100000) split inputs.
// ---------------------------------------------------------------------------
__global__ void pre_kernel(const float* __restrict__ xp, const float* __restrict__ xa,
                           __half* __restrict__ Ah,
                           float* __restrict__ acc, float* __restrict__ nrm) {
    int b = blockIdx.x;
    int t = threadIdx.x;
    if (b < 50000) {
        size_t i = (size_t)b * 256 + t;
        *(float4*)(acc + i * 4) = make_float4(0.f, 0.f, 0.f, 0.f);
        if (i < 2 * NNODES / 4)
            *(float4*)(nrm + i * 4) = make_float4(0.f, 0.f, 0.f, 0.f);
    } else {
        size_t gi = (size_t)(b - 50000) * 256 + t;
        int row = (int)(gi >> 6), c4 = (int)(gi & 63);
        const float* x = (row < NNODES) ? xp : xa;
        int lr = (row < NNODES) ? row : row - NNODES;
        float4 v = *(const float4*)(x + (size_t)lr * 256 + c4 * 4);
        __half2* ap = (__half2*)(Ah + (size_t)row * 256 + c4 * 4);
        ap[0] = __floats2half2_rn(v.x, v.y);
        ap[1] = __floats2half2_rn(v.z, v.w);
    }
}

__global__ void split_agg(const float* __restrict__ acc, const float* __restrict__ nrm,
                          __half* __restrict__ Ah) {
    size_t i = (size_t)blockIdx.x * 256 + threadIdx.x;
    int row = (int)(i >> 6), c4 = (int)(i & 63);
    float inv = 1.0f / fmaxf(nrm[row], 1e-8f);
    float4 v = *(const float4*)(acc + (size_t)row * 256 + c4 * 4);
    __half2* ap = (__half2*)(Ah + (size_t)row * 256 + c4 * 4);
    ap[0] = __floats2half2_rn(v.x * inv, v.y * inv);
    ap[1] = __floats2half2_rn(v.z * inv, v.w * inv);
}

// ---------------------------------------------------------------------------
// Edge kernel (proven 3-launch version): fp16 q/k/v gathers, red.v4 scatter.
// ---------------------------------------------------------------------------
static __device__ __forceinline__ float dot8h(uint4 a, uint4 b) {
    const __half2* ah = (const __half2*)&a;
    const __half2* bh = (const __half2*)&b;
    float p = 0.0f;
#pragma unroll
    for (int i = 0; i < 4; i++) {
        float2 af = __half22float2(ah[i]);
        float2 bf = __half22float2(bh[i]);
        p += af.x * bf.x + af.y * bf.y;
    }
    return p;
}

__global__ void __launch_bounds__(256) edge_kernel(
    const __half* __restrict__ qR, const __half* __restrict__ Ksrc,
    const __half* __restrict__ Vsrc, const int* __restrict__ ei,
    float* __restrict__ accum, float* __restrict__ nrm)
{
    const int lane = threadIdx.x & 31;
    const int warp = (blockIdx.x * blockDim.x + threadIdx.x) >> 5;
    const int nwarps = (gridDim.x * blockDim.x) >> 5;
    const int off = lane * 8;

    for (int e = warp; e < NEDGE; e += nwarps) {
        int src = __ldg(&ei[e]);
        int dst = __ldg(&ei[NEDGE + e]);

        uint4 qv = *(const uint4*)(qR + (size_t)dst * 256 + off);
        uint4 kv = *(const uint4*)(Ksrc + (size_t)src * 256 + off);
        float p = dot8h(qv, kv);
        p += __shfl_xor_sync(0xffffffffu, p, 1);
        p += __shfl_xor_sync(0xffffffffu, p, 2);

        float s = p * 0.17677669529663687f;
        s = fminf(fmaxf(s, -5.0f), 5.0f);
        float a = expf(s);

        uint4 vv = *(const uint4*)(Vsrc + (size_t)src * 256 + off);
        const __half2* vh = (const __half2*)&vv;
        float2 f0 = __half22float2(vh[0]);
        float2 f1 = __half22float2(vh[1]);
        float2 f2 = __half22float2(vh[2]);
        float2 f3 = __half22float2(vh[3]);
        float4 v0 = make_float4(f0.x * a, f0.y * a, f1.x * a, f1.y * a);
        float4 v1 = make_float4(f2.x * a, f2.y * a, f3.x * a, f3.y * a);

        float* arow = accum + (size_t)dst * 256 + off;
        REDV4(arow, v0);
        REDV4(arow + 4, v1);

        float w = a;
#pragma unroll
        for (int o = 16; o; o >>= 1) w += __shfl_xor_sync(0xffffffffu, w, o);
        if (lane == 0)
            atomicAdd(&nrm[dst], w * 0.03125f);
    }
}

// ---------------------------------------------------------------------------
extern "C" void kernel_launch(void* const* d_in, const int* in_sizes, int n_in,
                              void* d_out, int out_size) {
    const float* x_p   = (const float*)d_in[0];
    const float* x_a   = (const float*)d_in[1];
    const float* Wk_p  = (const float*)d_in[2];
    const float* bk_p  = (const float*)d_in[3];
    const float* Wq_p  = (const float*)d_in[4];
    const float* bq_p  = (const float*)d_in[5];
    const float* Wv_p  = (const float*)d_in[6];
    const float* bv_p  = (const float*)d_in[7];
    const float* Wo_p  = (const float*)d_in[8];
    const float* bo_p  = (const float*)d_in[9];
    const float* g_p   = (const float*)d_in[10];
    const float* be_p  = (const float*)d_in[11];
    const float* Wk_a  = (const float*)d_in[12];
    const float* bk_a  = (const float*)d_in[13];
    const float* Wq_a  = (const float*)d_in[14];
    const float* bq_a  = (const float*)d_in[15];
    const float* Wv_a  = (const float*)d_in[16];
    const float* bv_a  = (const float*)d_in[17];
    const float* Wo_a  = (const float*)d_in[18];
    const float* bo_a  = (const float*)d_in[19];
    const float* g_a   = (const float*)d_in[20];
    const float* be_a  = (const float*)d_in[21];
    const float* R_w   = (const float*)d_in[22];
    const int*   ei_w  = (const int*)d_in[23];
    const float* R_c   = (const float*)d_in[24];
    const int*   ei_c  = (const int*)d_in[25];
    const float* R_wb  = (const float*)d_in[26];
    const int*   ei_wb = (const int*)d_in[27];
    float* out = (float*)d_out;

    float* buf = nullptr; float* nrm = nullptr; __half* bufh = nullptr;
    __half* acath = nullptr; __half* bcath = nullptr;
    float* bias = nullptr;
    cudaGetSymbolAddress((void**)&buf, g_buf);
    cudaGetSymbolAddress((void**)&bufh, g_bufh);
    cudaGetSymbolAddress((void**)&nrm, g_norm);
    cudaGetSymbolAddress((void**)&acath, g_acath);
    cudaGetSymbolAddress((void**)&bcath, g_bcath);
    cudaGetSymbolAddress((void**)&bias, g_biascat);

    cudaFuncSetAttribute(gemm_score, cudaFuncAttributeMaxDynamicSharedMemorySize, SCORE_SMEM);
    cudaFuncSetAttribute(gemm_v,     cudaFuncAttributeMaxDynamicSharedMemorySize, GEMM_SMEM);
    cudaFuncSetAttribute(gemm_out_ln, cudaFuncAttributeMaxDynamicSharedMemorySize, OUT_SMEM);

    float* accp = buf;
    float* acca = buf + NB;
    __half* Kph   = bufh + 0 * NB;
    __half* Vph   = bufh + 1 * NB;
    __half* qRwh  = bufh + 2 * NB;
    __half* qRch  = bufh + 3 * NB;
    __half* Kah   = bufh + 4 * NB;
    __half* Vah   = bufh + 5 * NB;
    __half* qRwbh = bufh + 6 * NB;
    float* np_  = nrm;
    float* na_  = nrm + NNODES;

    __half* Ah0 = acath;
    __half* Ah1 = acath + (size_t)NNODES * 256;
#define BCH(i) (bcath + (size_t)(i) * 65536)

    PrepP P = {Wk_p, Wv_p, Wq_p, bq_p, Wo_p,
               Wk_a, Wv_a, Wq_a, bq_a, Wo_a,
               R_w, R_c, R_wb, bk_p, bv_p, bk_a, bv_a};

    // 1: zero + split inputs (fused)
    pre_kernel<<<100000, 256>>>(x_p, x_a, acath, accp, nrm);
    // 2: weight prep
    dim3 pg(257, 9);
    prep_all<<<pg, 256>>>(P, bcath, bias);

    // 3-4: projections (score: 256thr warp-tile 64x64; V: f32-acc)
    const int GX = (NNODES + 127) / 128;
    dim3 gs(GX, 5);
    gemm_score<<<gs, 256, SCORE_SMEM>>>(Ah0, Ah1, bcath, bias, bufh, NNODES);
    dim3 gv(GX, 4);
    gemm_v<<<gv, 256, GEMM_SMEM>>>(Ah0, Ah1, bcath, bias, bufh, NNODES);

    // 5-7: edge message passing (3 launches — proven optimum)
    edge_kernel<<<2048, 256>>>(qRwh,  Kah, Vah, ei_w,  accp, np_);
    edge_kernel<<<2048, 256>>>(qRch,  Kph, Vph, ei_c,  accp, np_);
    edge_kernel<<<2048, 256>>>(qRwbh, Kph, Vph, ei_wb, acca, na_);

    // 8: normalize + convert aggregates to fp16
    split_agg<<<2 * NNODES / 4, 256>>>(accp, nrm, acath);

    // 9: output GEMM + residual + LayerNorm
    OutP OP = {Ah0, Ah1, BCH(7), BCH(8), bo_p, bo_a, x_p, x_a, g_p, g_a, be_p, be_a};
    dim3 go(GX, 2);
    gemm_out_ln<<<go, 512, OUT_SMEM>>>(OP, out, NNODES);
}